// round 15
// baseline (speedup 1.0000x reference)
#include <cuda_runtime.h>
#include <cuda_fp16.h>
#include <mma.h>
using namespace nvcuda;

#define NUM_DRUG 50000
#define NUM_CELL 20000
#define HDIM     128
#define NEDGE    600000
#define NBATCH   4096

#define ND_TILES ((NUM_DRUG + 127) / 128)   // 391
#define NC_TILES ((NUM_CELL + 127) / 128)   // 157
#define MMA_GRID (ND_TILES + NC_TILES)      // 548

// wmma kernel smem: W fp16 32KB | X fp16 32KB (C fp32 64KB overlaps X)
#define WS_BYTES 32768
#define MMA_SMEM (WS_BYTES + 65536)         // 96 KB

// ---------------- scratch (device globals; no runtime allocation) ----------
__device__ __align__(16) float g_hA_drug[NUM_DRUG * HDIM];
__device__ __align__(16) float g_hA_cell[NUM_CELL * HDIM];
__device__ __align__(16) float g_hB_drug[NUM_DRUG * HDIM];
__device__ __align__(16) float g_hB_cell[NUM_CELL * HDIM];
__device__ __align__(16) __half g_acc16[(NUM_DRUG + NUM_CELL) * HDIM];  // fp16 means
__device__ __align__(16) __half g_he_drug[NUM_DRUG * HDIM];   // fp16 gather tables
__device__ __align__(16) __half g_he_cell[NUM_CELL * HDIM];
__device__ __align__(16) __half g_h1_drug[NUM_DRUG * HDIM];
__device__ __align__(16) __half g_h1_cell[NUM_CELL * HDIM];
__device__ __align__(16) __half g_Wh_td[HDIM * HDIM];   // fp16 copy of W (row-major [out][k])
__device__ __align__(16) __half g_Wh_dt[HDIM * HDIM];
__device__ int g_off_drug[NUM_DRUG + 1];
__device__ int g_off_cell[NUM_CELL + 1];
__device__ int g_cur_drug[NUM_DRUG];
__device__ int g_cur_cell[NUM_CELL];
__device__ int g_csr_td[NEDGE];
__device__ int g_csr_dt[NEDGE];

// ---------------- helpers ----------------------------------------------------
__device__ __forceinline__ unsigned long long addf2(unsigned long long a,
                                                    unsigned long long b) {
    unsigned long long d;
    asm("add.rn.f32x2 %0, %1, %2;" : "=l"(d) : "l"(a), "l"(b));
    return d;
}
__device__ __forceinline__ float lo2(unsigned long long v) {
    return __uint_as_float((unsigned)(v & 0xffffffffull));
}
__device__ __forceinline__ float hi2(unsigned long long v) {
    return __uint_as_float((unsigned)(v >> 32));
}
__device__ __forceinline__ unsigned long long h2f2(unsigned h) {
    float2 f = __half22float2(*reinterpret_cast<const __half2*>(&h));
    unsigned long long r;
    asm("mov.b64 %0, {%1, %2};" : "=l"(r) : "f"(f.x), "f"(f.y));
    return r;
}

// ---------------- CSR hist ---------------------------------------------------
#define EB2 ((2 * NEDGE + 255) / 256)
__global__ void hist_kernel(const int* __restrict__ dstA, int* __restrict__ cntA,
                            const int* __restrict__ dstB, int* __restrict__ cntB)
{
    int i = blockIdx.x * blockDim.x + threadIdx.x;
    if (i < NEDGE)               atomicAdd(&cntA[dstA[i]], 1);
    else if (i < 2 * NEDGE)      atomicAdd(&cntB[dstB[i - NEDGE]], 1);
}

// ---------------- emb -> fp16 tables -----------------------------------------
#define CONVB (((NUM_DRUG + NUM_CELL) * HDIM / 4) / 256)      // 8750 blocks
__global__ void conv_kernel(const float* __restrict__ ed, __half* __restrict__ hd16,
                            const float* __restrict__ ec, __half* __restrict__ hc16)
{
    int j = blockIdx.x * blockDim.x + threadIdx.x;   // float4 index
    const int nd4 = NUM_DRUG * HDIM / 4;
    const int nc4 = NUM_CELL * HDIM / 4;
    if (j < nd4) {
        float4 v = reinterpret_cast<const float4*>(ed)[j];
        uint2 o;
        *reinterpret_cast<__half2*>(&o.x) = __floats2half2_rn(v.x, v.y);
        *reinterpret_cast<__half2*>(&o.y) = __floats2half2_rn(v.z, v.w);
        reinterpret_cast<uint2*>(hd16)[j] = o;
    } else if (j < nd4 + nc4) {
        int k = j - nd4;
        float4 v = reinterpret_cast<const float4*>(ec)[k];
        uint2 o;
        *reinterpret_cast<__half2*>(&o.x) = __floats2half2_rn(v.x, v.y);
        *reinterpret_cast<__half2*>(&o.y) = __floats2half2_rn(v.z, v.w);
        reinterpret_cast<uint2*>(hc16)[k] = o;
    }
}

// blocks 0,1: coarsened scans. blocks 2,3: W -> fp16 copy (row-major kept).
__global__ void scan_prep_kernel(const int* __restrict__ cntA, int* __restrict__ offA,
                                 const int* __restrict__ cntB, int* __restrict__ offB,
                                 const float* __restrict__ Wa, __half* __restrict__ WhA,
                                 const float* __restrict__ Wb, __half* __restrict__ WhB)
{
    int t = threadIdx.x;
    if (blockIdx.x >= 2) {
        const float* W = blockIdx.x == 2 ? Wa : Wb;
        __half* Wh     = blockIdx.x == 2 ? WhA : WhB;
        #pragma unroll
        for (int i = t; i < HDIM * HDIM; i += 1024)
            Wh[i] = __float2half(W[i]);
        return;
    }
    const int* cnt = blockIdx.x == 0 ? cntA : cntB;
    int* off       = blockIdx.x == 0 ? offA : offB;
    const int n    = blockIdx.x == 0 ? NUM_DRUG : NUM_CELL;

    __shared__ int ws[32];
    __shared__ int s_carry;
    int lane = t & 31, w = t >> 5;
    if (t == 0) s_carry = 0;
    __syncthreads();

    for (int base = 0; base < n; base += 1024 * 8) {
        int idx = base + t * 8;
        int v[8];
        #pragma unroll
        for (int j = 0; j < 8; j++)
            v[j] = (idx + j < n) ? cnt[idx + j] : 0;
        #pragma unroll
        for (int j = 1; j < 8; j++) v[j] += v[j - 1];
        int tot = v[7];
        int x = tot;
        #pragma unroll
        for (int o = 1; o < 32; o <<= 1) {
            int y = __shfl_up_sync(0xffffffffu, x, o);
            if (lane >= o) x += y;
        }
        if (lane == 31) ws[w] = x;
        __syncthreads();
        if (w == 0) {
            int s = ws[lane];
            #pragma unroll
            for (int o = 1; o < 32; o <<= 1) {
                int y = __shfl_up_sync(0xffffffffu, s, o);
                if (lane >= o) s += y;
            }
            ws[lane] = s;
        }
        __syncthreads();
        int prefix = (x - tot) + (w ? ws[w - 1] : 0) + s_carry;
        #pragma unroll
        for (int j = 0; j < 8; j++)
            if (idx + j < n) off[idx + j + 1] = prefix + v[j];
        __syncthreads();
        if (t == 0) s_carry += ws[31];
        __syncthreads();
    }
    if (t == 0) off[0] = 0;
}

__global__ void fill2_kernel(const int* __restrict__ srcA, const int* __restrict__ dstA,
                             const int* __restrict__ offA, int* __restrict__ curA,
                             int* __restrict__ csrA,
                             const int* __restrict__ srcB, const int* __restrict__ dstB,
                             const int* __restrict__ offB, int* __restrict__ curB,
                             int* __restrict__ csrB)
{
    int tid = blockIdx.x * blockDim.x + threadIdx.x;
    int i0 = tid * 2;
    if (i0 < NEDGE) {
        int i1 = i0 + 1;
        int d0 = dstA[i0];
        int d1 = (i1 < NEDGE) ? dstA[i1] : -1;
        int s0 = srcA[i0];
        int s1 = (i1 < NEDGE) ? srcA[i1] : 0;
        int p0 = offA[d0] + atomicAdd(&curA[d0], 1);
        int p1 = (d1 >= 0) ? (offA[d1] + atomicAdd(&curA[d1], 1)) : 0;
        csrA[p0] = s0;
        if (d1 >= 0) csrA[p1] = s1;
    } else if (i0 < 2 * NEDGE) {
        int j0 = i0 - NEDGE, j1 = j0 + 1;
        int d0 = dstB[j0];
        int d1 = (j1 < NEDGE) ? dstB[j1] : -1;
        int s0 = srcB[j0];
        int s1 = (j1 < NEDGE) ? srcB[j1] : 0;
        int p0 = offB[d0] + atomicAdd(&curB[d0], 1);
        int p1 = (d1 >= 0) ? (offB[d1] + atomicAdd(&curB[d1], 1)) : 0;
        csrB[p0] = s0;
        if (d1 >= 0) csrB[p1] = s1;
    }
}

// ---------------- dual-row gather-mean -> fp16 acc ---------------------------
#define GACC4(vx, AXY, AZW) { AXY = addf2(AXY, h2f2((vx).x)); AZW = addf2(AZW, h2f2((vx).y)); }

__global__ void gather2_kernel(const __half* __restrict__ hd16,
                               const __half* __restrict__ hc16,
                               __half* __restrict__ acc16,
                               const int* __restrict__ off_d, const int* __restrict__ csr_d,
                               const int* __restrict__ off_c, const int* __restrict__ csr_c)
{
    const int task = (blockIdx.x * blockDim.x + threadIdx.x) >> 5;
    const int lane = threadIdx.x & 31;
    const int rA = task * 2, rB = rA + 1;

    const uint2 *sA, *sB; const int *oA, *oB, *cAp, *cBp; int ra, rb;
    if (rA < NUM_DRUG) { sA = (const uint2*)hc16; oA = off_d; cAp = csr_d; ra = rA; }
    else               { sA = (const uint2*)hd16; oA = off_c; cAp = csr_c; ra = rA - NUM_DRUG; }
    if (rB < NUM_DRUG) { sB = (const uint2*)hc16; oB = off_d; cBp = csr_d; rb = rB; }
    else               { sB = (const uint2*)hd16; oB = off_c; cBp = csr_c; rb = rB - NUM_DRUG; }

    int jA = oA[ra], eA = oA[ra + 1];
    int jB = oB[rb], eB = oB[rb + 1];

    unsigned long long Axy0 = 0, Axy1 = 0, Azw0 = 0, Azw1 = 0;
    unsigned long long Bxy0 = 0, Bxy1 = 0, Bzw0 = 0, Bzw1 = 0;

    while (jA + 8 <= eA && jB + 8 <= eB) {
        int a0 = cAp[jA],   a1 = cAp[jA+1], a2 = cAp[jA+2], a3 = cAp[jA+3];
        int a4 = cAp[jA+4], a5 = cAp[jA+5], a6 = cAp[jA+6], a7 = cAp[jA+7];
        int b0 = cBp[jB],   b1 = cBp[jB+1], b2 = cBp[jB+2], b3 = cBp[jB+3];
        int b4 = cBp[jB+4], b5 = cBp[jB+5], b6 = cBp[jB+6], b7 = cBp[jB+7];
        uint2 va0 = sA[a0*32+lane], va1 = sA[a1*32+lane], va2 = sA[a2*32+lane], va3 = sA[a3*32+lane];
        uint2 va4 = sA[a4*32+lane], va5 = sA[a5*32+lane], va6 = sA[a6*32+lane], va7 = sA[a7*32+lane];
        uint2 vb0 = sB[b0*32+lane], vb1 = sB[b1*32+lane], vb2 = sB[b2*32+lane], vb3 = sB[b3*32+lane];
        uint2 vb4 = sB[b4*32+lane], vb5 = sB[b5*32+lane], vb6 = sB[b6*32+lane], vb7 = sB[b7*32+lane];
        GACC4(va0, Axy0, Azw0); GACC4(va1, Axy1, Azw1);
        GACC4(va2, Axy0, Azw0); GACC4(va3, Axy1, Azw1);
        GACC4(va4, Axy0, Azw0); GACC4(va5, Axy1, Azw1);
        GACC4(va6, Axy0, Azw0); GACC4(va7, Axy1, Azw1);
        GACC4(vb0, Bxy0, Bzw0); GACC4(vb1, Bxy1, Bzw1);
        GACC4(vb2, Bxy0, Bzw0); GACC4(vb3, Bxy1, Bzw1);
        GACC4(vb4, Bxy0, Bzw0); GACC4(vb5, Bxy1, Bzw1);
        GACC4(vb6, Bxy0, Bzw0); GACC4(vb7, Bxy1, Bzw1);
        jA += 8; jB += 8;
    }
    while (jA + 4 <= eA) {
        int a0 = cAp[jA], a1 = cAp[jA+1], a2 = cAp[jA+2], a3 = cAp[jA+3];
        uint2 v0 = sA[a0*32+lane], v1 = sA[a1*32+lane], v2 = sA[a2*32+lane], v3 = sA[a3*32+lane];
        GACC4(v0, Axy0, Azw0); GACC4(v1, Axy1, Azw1);
        GACC4(v2, Axy0, Azw0); GACC4(v3, Axy1, Azw1);
        jA += 4;
    }
    for (; jA < eA; jA++) { uint2 v = sA[cAp[jA]*32+lane]; GACC4(v, Axy0, Azw0); }
    while (jB + 4 <= eB) {
        int b0 = cBp[jB], b1 = cBp[jB+1], b2 = cBp[jB+2], b3 = cBp[jB+3];
        uint2 v0 = sB[b0*32+lane], v1 = sB[b1*32+lane], v2 = sB[b2*32+lane], v3 = sB[b3*32+lane];
        GACC4(v0, Bxy0, Bzw0); GACC4(v1, Bxy1, Bzw1);
        GACC4(v2, Bxy0, Bzw0); GACC4(v3, Bxy1, Bzw1);
        jB += 4;
    }
    for (; jB < eB; jB++) { uint2 v = sB[cBp[jB]*32+lane]; GACC4(v, Bxy0, Bzw0); }

    unsigned long long AXY = addf2(Axy0, Axy1), AZW = addf2(Azw0, Azw1);
    unsigned long long BXY = addf2(Bxy0, Bxy1), BZW = addf2(Bzw0, Bzw1);
    int dA = eA - oA[ra];
    int dB = eB - oB[rb];
    float invA = 1.0f / (float)(dA < 1 ? 1 : dA);
    float invB = 1.0f / (float)(dB < 1 ? 1 : dB);
    uint2 pa, pb;
    *reinterpret_cast<__half2*>(&pa.x) = __floats2half2_rn(lo2(AXY) * invA, hi2(AXY) * invA);
    *reinterpret_cast<__half2*>(&pa.y) = __floats2half2_rn(lo2(AZW) * invA, hi2(AZW) * invA);
    *reinterpret_cast<__half2*>(&pb.x) = __floats2half2_rn(lo2(BXY) * invB, hi2(BXY) * invB);
    *reinterpret_cast<__half2*>(&pb.y) = __floats2half2_rn(lo2(BZW) * invB, hi2(BZW) * invB);
    reinterpret_cast<uint2*>(acc16)[rA * 32 + lane] = pa;
    reinterpret_cast<uint2*>(acc16)[rB * 32 + lane] = pb;
}

// ---------------- wmma GEMM tile + residual + LN + ReLU ----------------------
// One CTA = one 128-row tile. D[m][n] = sum_k X[m][k] * W[n][k].
// W row-major [n][k] == col-major k x n with ld=128 -> matrix_b col_major direct.
__global__ void __launch_bounds__(256)
wmma_ln_kernel(const __half* __restrict__ acc16,
               const float* __restrict__ hd_in, const float* __restrict__ hc_in,
               float* __restrict__ hd_out, float* __restrict__ hc_out,
               __half* __restrict__ hd16_out, __half* __restrict__ hc16_out,
               const __half* __restrict__ Wh_td, const __half* __restrict__ Wh_dt,
               const float* __restrict__ gd, const float* __restrict__ bd,
               const float* __restrict__ gc, const float* __restrict__ bc,
               int write16)
{
    const bool isD = blockIdx.x < ND_TILES;
    const int tile = isD ? blockIdx.x : blockIdx.x - ND_TILES;
    const int row0 = tile * 128;
    const int nside = isD ? NUM_DRUG : NUM_CELL;
    const int rows  = min(128, nside - row0);
    const __half* accp = acc16 + (isD ? 0 : (size_t)NUM_DRUG * HDIM);
    const float* hold  = isD ? hd_in : hc_in;
    float* outp        = isD ? hd_out : hc_out;
    __half* outp16     = isD ? hd16_out : hc16_out;
    const __half* Wh   = isD ? Wh_td : Wh_dt;
    const float4* gam4 = reinterpret_cast<const float4*>(isD ? gd : gc);
    const float4* bet4 = reinterpret_cast<const float4*>(isD ? bd : bc);

    extern __shared__ char smem[];
    __half* Ws = reinterpret_cast<__half*>(smem);               // [128][128] fp16
    __half* Xs = reinterpret_cast<__half*>(smem + WS_BYTES);    // [128][128] fp16
    float*  Cs = reinterpret_cast<float*>(smem + WS_BYTES);     // [128][128] fp32 (overlaps Xs)

    const int t = threadIdx.x, w = t >> 5, lane = t & 31;

    // stage W (flat fp16 copy) and X (fp16 means; zero-pad partial tile)
    for (int i = t; i < 2048; i += 256)
        reinterpret_cast<uint4*>(Ws)[i] = reinterpret_cast<const uint4*>(Wh)[i];
    {
        const uint2 z2 = {0u, 0u};
        for (int i = t; i < 128 * 32; i += 256) {
            int r = i >> 5, q = i & 31;
            reinterpret_cast<uint2*>(Xs)[i] =
                (r < rows) ? reinterpret_cast<const uint2*>(accp)[(row0 + r) * 32 + q] : z2;
        }
    }
    __syncthreads();

    // warp w: rows w*16 .. w*16+15; 8 accumulator tiles over 128 cols
    wmma::fragment<wmma::accumulator, 16, 16, 16, float> c[8];
    #pragma unroll
    for (int j = 0; j < 8; j++) wmma::fill_fragment(c[j], 0.0f);

    #pragma unroll
    for (int k0 = 0; k0 < 8; k0++) {
        wmma::fragment<wmma::matrix_a, 16, 16, 16, __half, wmma::row_major> a;
        wmma::load_matrix_sync(a, Xs + (w * 16) * HDIM + k0 * 16, HDIM);
        #pragma unroll
        for (int j = 0; j < 8; j++) {
            wmma::fragment<wmma::matrix_b, 16, 16, 16, __half, wmma::col_major> b;
            wmma::load_matrix_sync(b, Ws + (j * 16) * HDIM + k0 * 16, HDIM);
            wmma::mma_sync(c[j], a, b, c[j]);
        }
    }
    __syncthreads();   // all X reads done before C overwrites Xs

    #pragma unroll
    for (int j = 0; j < 8; j++)
        wmma::store_matrix_sync(Cs + (w * 16) * HDIM + j * 16, c[j], HDIM,
                                wmma::mem_row_major);
    __syncthreads();

    // epilogue: warp w handles rows w*16..w*16+15; per-row warp LN
    const float4 g4 = __ldg(&gam4[lane]);
    const float4 b4 = __ldg(&bet4[lane]);
    const float4* hold4 = reinterpret_cast<const float4*>(hold);
    float4* out4        = reinterpret_cast<float4*>(outp);
    uint2* out16        = reinterpret_cast<uint2*>(outp16);

    for (int i = 0; i < 16; i++) {
        int lrow = w * 16 + i;
        if (lrow >= rows) break;
        int grow = row0 + lrow;
        float4 cv = *reinterpret_cast<const float4*>(Cs + lrow * HDIM + lane * 4);
        float4 hv = hold4[grow * 32 + lane];
        float y0 = cv.x + hv.x, y1 = cv.y + hv.y, y2 = cv.z + hv.z, y3 = cv.w + hv.w;

        float s = y0 + y1 + y2 + y3;
        float q = y0*y0 + y1*y1 + y2*y2 + y3*y3;
        #pragma unroll
        for (int o = 16; o; o >>= 1) {
            s += __shfl_xor_sync(0xffffffffu, s, o);
            q += __shfl_xor_sync(0xffffffffu, q, o);
        }
        float mu  = s * (1.0f / HDIM);
        float var = q * (1.0f / HDIM) - mu * mu;
        float rs  = rsqrtf(var + 1e-5f);
        float4 o4;
        o4.x = (y0 - mu) * rs * g4.x + b4.x; o4.x = o4.x > 0.f ? o4.x : 0.f;
        o4.y = (y1 - mu) * rs * g4.y + b4.y; o4.y = o4.y > 0.f ? o4.y : 0.f;
        o4.z = (y2 - mu) * rs * g4.z + b4.z; o4.z = o4.z > 0.f ? o4.z : 0.f;
        o4.w = (y3 - mu) * rs * g4.w + b4.w; o4.w = o4.w > 0.f ? o4.w : 0.f;
        out4[grow * 32 + lane] = o4;
        if (write16) {
            uint2 p;
            *reinterpret_cast<__half2*>(&p.x) = __floats2half2_rn(o4.x, o4.y);
            *reinterpret_cast<__half2*>(&p.y) = __floats2half2_rn(o4.z, o4.w);
            out16[grow * 32 + lane] = p;
        }
    }
}

// ---------------- final head -------------------------------------------------
__global__ void final_kernel(const float* __restrict__ hd,
                             const float* __restrict__ hc,
                             const int* __restrict__ did,
                             const int* __restrict__ cid,
                             const float* __restrict__ wf,
                             const float* __restrict__ bf,
                             float* __restrict__ out, int nb)
{
    int warp = (blockIdx.x * blockDim.x + threadIdx.x) >> 5;
    int lane = threadIdx.x & 31;
    if (warp >= nb) return;
    int d = did[warp], c = cid[warp];
    float4 a  = reinterpret_cast<const float4*>(hd)[d * 32 + lane];
    float4 w1 = reinterpret_cast<const float4*>(wf)[lane];
    float4 b4 = reinterpret_cast<const float4*>(hc)[c * 32 + lane];
    float4 w2 = reinterpret_cast<const float4*>(wf)[32 + lane];
    float s = a.x * w1.x + a.y * w1.y + a.z * w1.z + a.w * w1.w
            + b4.x * w2.x + b4.y * w2.y + b4.z * w2.z + b4.w * w2.w;
    #pragma unroll
    for (int o = 16; o; o >>= 1) s += __shfl_xor_sync(0xffffffffu, s, o);
    if (lane == 0) {
        float x = s + bf[0];
        out[warp] = 1.0f / (1.0f + expf(-x));
    }
}

// ---------------------------------------------------------------------------
extern "C" void kernel_launch(void* const* d_in, const int* in_sizes, int n_in,
                              void* d_out, int out_size)
{
    const float* emb_drug  = (const float*)d_in[0];
    const float* emb_cell  = (const float*)d_in[1];
    const float* W_dt      = (const float*)d_in[2];
    const float* W_td      = (const float*)d_in[3];
    const float* ln_drug_g = (const float*)d_in[4];
    const float* ln_drug_b = (const float*)d_in[5];
    const float* ln_cell_g = (const float*)d_in[6];
    const float* ln_cell_b = (const float*)d_in[7];
    const float* W_final_w = (const float*)d_in[8];
    const float* W_final_b = (const float*)d_in[9];
    const int* edge_dt_src = (const int*)d_in[10];
    const int* edge_dt_dst = (const int*)d_in[11];
    const int* edge_td_src = (const int*)d_in[12];
    const int* edge_td_dst = (const int*)d_in[13];
    const int* drug_ids    = (const int*)d_in[14];
    const int* cell_ids    = (const int*)d_in[15];
    float* out = (float*)d_out;

    float *hA_d, *hA_c, *hB_d, *hB_c;
    __half *acc16, *he_d, *he_c, *h1_d, *h1_c, *Wh_td, *Wh_dt;
    int *off_d, *off_c, *cur_d, *cur_c, *csr_td, *csr_dt;
    cudaGetSymbolAddress((void**)&hA_d,   g_hA_drug);
    cudaGetSymbolAddress((void**)&hA_c,   g_hA_cell);
    cudaGetSymbolAddress((void**)&hB_d,   g_hB_drug);
    cudaGetSymbolAddress((void**)&hB_c,   g_hB_cell);
    cudaGetSymbolAddress((void**)&acc16,  g_acc16);
    cudaGetSymbolAddress((void**)&he_d,   g_he_drug);
    cudaGetSymbolAddress((void**)&he_c,   g_he_cell);
    cudaGetSymbolAddress((void**)&h1_d,   g_h1_drug);
    cudaGetSymbolAddress((void**)&h1_c,   g_h1_cell);
    cudaGetSymbolAddress((void**)&Wh_td,  g_Wh_td);
    cudaGetSymbolAddress((void**)&Wh_dt,  g_Wh_dt);
    cudaGetSymbolAddress((void**)&off_d,  g_off_drug);
    cudaGetSymbolAddress((void**)&off_c,  g_off_cell);
    cudaGetSymbolAddress((void**)&cur_d,  g_cur_drug);
    cudaGetSymbolAddress((void**)&cur_c,  g_cur_cell);
    cudaGetSymbolAddress((void**)&csr_td, g_csr_td);
    cudaGetSymbolAddress((void**)&csr_dt, g_csr_dt);

    cudaFuncSetAttribute(wmma_ln_kernel,
                         cudaFuncAttributeMaxDynamicSharedMemorySize,
                         (int)MMA_SMEM);

    const int gather_blocks = ((NUM_DRUG + NUM_CELL) / 2) / 4;   // 8750

    // ---------------- CSR build + fp16 prep ----------------
    cudaMemsetAsync(cur_d, 0, NUM_DRUG * sizeof(int));
    cudaMemsetAsync(cur_c, 0, NUM_CELL * sizeof(int));
    hist_kernel<<<EB2, 256>>>(edge_td_dst, cur_d, edge_dt_dst, cur_c);
    conv_kernel<<<CONVB, 256>>>(emb_drug, he_d, emb_cell, he_c);
    scan_prep_kernel<<<4, 1024>>>(cur_d, off_d, cur_c, off_c,
                                  W_td, Wh_td, W_dt, Wh_dt);
    cudaMemsetAsync(cur_d, 0, NUM_DRUG * sizeof(int));
    cudaMemsetAsync(cur_c, 0, NUM_CELL * sizeof(int));
    fill2_kernel<<<(NEDGE + 255) / 256, 256>>>(
        edge_td_src, edge_td_dst, off_d, cur_d, csr_td,
        edge_dt_src, edge_dt_dst, off_c, cur_c, csr_dt);

    // ---------------- layer 0 ----------------
    gather2_kernel<<<gather_blocks, 128>>>(he_d, he_c, acc16,
                                           off_d, csr_td, off_c, csr_dt);
    wmma_ln_kernel<<<MMA_GRID, 256, MMA_SMEM>>>(
        acc16, emb_drug, emb_cell, hA_d, hA_c, h1_d, h1_c,
        Wh_td, Wh_dt, ln_drug_g, ln_drug_b, ln_cell_g, ln_cell_b, 1);

    // ---------------- layer 1 ----------------
    gather2_kernel<<<gather_blocks, 128>>>(h1_d, h1_c, acc16,
                                           off_d, csr_td, off_c, csr_dt);
    wmma_ln_kernel<<<MMA_GRID, 256, MMA_SMEM>>>(
        acc16, hA_d, hA_c, hB_d, hB_c, h1_d, h1_c,
        Wh_td, Wh_dt, ln_drug_g, ln_drug_b, ln_cell_g, ln_cell_b, 0);

    // ---------------- final head ----------------
    final_kernel<<<(NBATCH * 32) / 256, 256>>>(hB_d, hB_c, drug_ids, cell_ids,
                                               W_final_w, W_final_b, out, NBATCH);
}

// round 16
// speedup vs baseline: 1.1892x; 1.1892x over previous
#include <cuda_runtime.h>
#include <cuda_fp16.h>

#define NUM_DRUG 50000
#define NUM_CELL 20000
#define HDIM     128
#define NEDGE    600000
#define NBATCH   4096

#define G8_DRUG (NUM_DRUG / 8)   // 6250 warp-tiles
#define G8_CELL (NUM_CELL / 8)   // 2500

#define GEMM_BLOCKS 296
#define ND_BLOCKS   212          // drug share of gemm blocks (50k/70k rows)
#define WARPS       8            // 256 threads / block
#define GEMM_SMEM ((HDIM * HDIM + WARPS * 8 * HDIM) * sizeof(float))  // 96 KB

// ---------------- scratch (device globals; no runtime allocation) ----------
__device__ __align__(16) float g_hA_drug[NUM_DRUG * HDIM];
__device__ __align__(16) float g_hA_cell[NUM_CELL * HDIM];
__device__ __align__(16) float g_hB_drug[NUM_DRUG * HDIM];
__device__ __align__(16) float g_hB_cell[NUM_CELL * HDIM];
__device__ __align__(16) float g_acc[(NUM_DRUG + NUM_CELL) * HDIM];  // mean msgs
__device__ __align__(16) __half g_he_drug[NUM_DRUG * HDIM];   // fp16 gather tables
__device__ __align__(16) __half g_he_cell[NUM_CELL * HDIM];
__device__ __align__(16) __half g_h1_drug[NUM_DRUG * HDIM];
__device__ __align__(16) __half g_h1_cell[NUM_CELL * HDIM];
__device__ __align__(16) float g_WT_td[HDIM * HDIM];
__device__ __align__(16) float g_WT_dt[HDIM * HDIM];
__device__ int g_off_drug[NUM_DRUG + 1];
__device__ int g_off_cell[NUM_CELL + 1];
__device__ int g_cur_drug[NUM_DRUG];
__device__ int g_cur_cell[NUM_CELL];
__device__ int g_rank_td[NEDGE];   // per-edge rank within its dst (drug side)
__device__ int g_rank_dt[NEDGE];   // per-edge rank within its dst (cell side)
__device__ int g_csr_td[NEDGE];
__device__ int g_csr_dt[NEDGE];

// ---------------- f32x2 helpers --------------------------------------------
__device__ __forceinline__ unsigned long long splat2(float x) {
    unsigned long long r; unsigned xi = __float_as_uint(x);
    asm("mov.b64 %0, {%1, %1};" : "=l"(r) : "r"(xi));
    return r;
}
__device__ __forceinline__ unsigned long long fma2(unsigned long long a,
                                                   unsigned long long b,
                                                   unsigned long long c) {
    unsigned long long d;
    asm("fma.rn.f32x2 %0, %1, %2, %3;" : "=l"(d) : "l"(a), "l"(b), "l"(c));
    return d;
}
__device__ __forceinline__ unsigned long long addf2(unsigned long long a,
                                                    unsigned long long b) {
    unsigned long long d;
    asm("add.rn.f32x2 %0, %1, %2;" : "=l"(d) : "l"(a), "l"(b));
    return d;
}
__device__ __forceinline__ float lo2(unsigned long long v) {
    return __uint_as_float((unsigned)(v & 0xffffffffull));
}
__device__ __forceinline__ float hi2(unsigned long long v) {
    return __uint_as_float((unsigned)(v >> 32));
}
__device__ __forceinline__ unsigned long long h2f2(unsigned h) {
    float2 f = __half22float2(*reinterpret_cast<const __half2*>(&h));
    unsigned long long r;
    asm("mov.b64 %0, {%1, %2};" : "=l"(r) : "f"(f.x), "f"(f.y));
    return r;
}

// ---------------- CSR hist (stores per-edge rank) + emb->fp16 convert ------
#define EB2   ((2 * NEDGE + 255) / 256)                       // 4688 blocks
#define CONVB (((NUM_DRUG + NUM_CELL) * HDIM / 4) / 256)      // 8750 blocks
__global__ void hist_conv_kernel(const int* __restrict__ dstA, int* __restrict__ cntA,
                                 int* __restrict__ rankA,
                                 const int* __restrict__ dstB, int* __restrict__ cntB,
                                 int* __restrict__ rankB,
                                 const float* __restrict__ ed, __half* __restrict__ hd16,
                                 const float* __restrict__ ec, __half* __restrict__ hc16)
{
    long long i = (long long)blockIdx.x * blockDim.x + threadIdx.x;
    if (i < NEDGE) { rankA[i] = atomicAdd(&cntA[dstA[i]], 1); return; }
    if (i < 2 * NEDGE) {
        long long j = i - NEDGE;
        rankB[j] = atomicAdd(&cntB[dstB[j]], 1);
        return;
    }
    long long j = i - 2 * NEDGE;   // float4 index
    const long long nd4 = (long long)NUM_DRUG * HDIM / 4;
    const long long nc4 = (long long)NUM_CELL * HDIM / 4;
    if (j < nd4) {
        float4 v = reinterpret_cast<const float4*>(ed)[j];
        uint2 o;
        *reinterpret_cast<__half2*>(&o.x) = __floats2half2_rn(v.x, v.y);
        *reinterpret_cast<__half2*>(&o.y) = __floats2half2_rn(v.z, v.w);
        reinterpret_cast<uint2*>(hd16)[j] = o;
    } else if (j < nd4 + nc4) {
        long long k = j - nd4;
        float4 v = reinterpret_cast<const float4*>(ec)[k];
        uint2 o;
        *reinterpret_cast<__half2*>(&o.x) = __floats2half2_rn(v.x, v.y);
        *reinterpret_cast<__half2*>(&o.y) = __floats2half2_rn(v.z, v.w);
        reinterpret_cast<uint2*>(hc16)[k] = o;
    }
}

// blocks 0,1: coarsened scans. blocks 2,3: weight transposes.
__global__ void scan_transpose_kernel(const int* __restrict__ cntA, int* __restrict__ offA,
                                      const int* __restrict__ cntB, int* __restrict__ offB,
                                      const float* __restrict__ Wa, float* __restrict__ WTa,
                                      const float* __restrict__ Wb, float* __restrict__ WTb)
{
    int t = threadIdx.x;
    if (blockIdx.x >= 2) {
        const float* W = blockIdx.x == 2 ? Wa : Wb;
        float* WT      = blockIdx.x == 2 ? WTa : WTb;
        #pragma unroll
        for (int i = t; i < HDIM * HDIM; i += 1024) {
            int k = i & 127, out = i >> 7;
            WT[k * HDIM + out] = W[out * HDIM + k];
        }
        return;
    }
    const int* cnt = blockIdx.x == 0 ? cntA : cntB;
    int* off       = blockIdx.x == 0 ? offA : offB;
    const int n    = blockIdx.x == 0 ? NUM_DRUG : NUM_CELL;

    __shared__ int ws[32];
    __shared__ int s_carry;
    int lane = t & 31, w = t >> 5;
    if (t == 0) s_carry = 0;
    __syncthreads();

    for (int base = 0; base < n; base += 1024 * 8) {
        int idx = base + t * 8;
        int v[8];
        #pragma unroll
        for (int j = 0; j < 8; j++)
            v[j] = (idx + j < n) ? cnt[idx + j] : 0;
        #pragma unroll
        for (int j = 1; j < 8; j++) v[j] += v[j - 1];
        int tot = v[7];
        int x = tot;
        #pragma unroll
        for (int o = 1; o < 32; o <<= 1) {
            int y = __shfl_up_sync(0xffffffffu, x, o);
            if (lane >= o) x += y;
        }
        if (lane == 31) ws[w] = x;
        __syncthreads();
        if (w == 0) {
            int s = ws[lane];
            #pragma unroll
            for (int o = 1; o < 32; o <<= 1) {
                int y = __shfl_up_sync(0xffffffffu, s, o);
                if (lane >= o) s += y;
            }
            ws[lane] = s;
        }
        __syncthreads();
        int prefix = (x - tot) + (w ? ws[w - 1] : 0) + s_carry;
        #pragma unroll
        for (int j = 0; j < 8; j++)
            if (idx + j < n) off[idx + j + 1] = prefix + v[j];
        __syncthreads();
        if (t == 0) s_carry += ws[31];
        __syncthreads();
    }
    if (t == 0) off[0] = 0;
}

// atomic-free fill: position = off[dst] + precomputed rank
__global__ void fill2_kernel(const int* __restrict__ srcA, const int* __restrict__ dstA,
                             const int* __restrict__ rankA,
                             const int* __restrict__ offA, int* __restrict__ csrA,
                             const int* __restrict__ srcB, const int* __restrict__ dstB,
                             const int* __restrict__ rankB,
                             const int* __restrict__ offB, int* __restrict__ csrB)
{
    int tid = blockIdx.x * blockDim.x + threadIdx.x;
    int i0 = tid * 2;
    if (i0 < NEDGE) {
        int i1 = i0 + 1;
        int d0 = dstA[i0];
        int d1 = (i1 < NEDGE) ? dstA[i1] : d0;
        int p0 = offA[d0] + rankA[i0];
        int p1 = (i1 < NEDGE) ? (offA[d1] + rankA[i1]) : -1;
        csrA[p0] = srcA[i0];
        if (p1 >= 0) csrA[p1] = srcA[i1];
    } else if (i0 < 2 * NEDGE) {
        int j0 = i0 - NEDGE, j1 = j0 + 1;
        int d0 = dstB[j0];
        int d1 = (j1 < NEDGE) ? dstB[j1] : d0;
        int p0 = offB[d0] + rankB[j0];
        int p1 = (j1 < NEDGE) ? (offB[d1] + rankB[j1]) : -1;
        csrB[p0] = srcB[j0];
        if (p1 >= 0) csrB[p1] = srcB[j1];
    }
}

// ---------------- dual-row gather-mean (fp16 src, fp32 accumulate) ---------
#define GACC4(vx, AXY, AZW) { AXY = addf2(AXY, h2f2((vx).x)); AZW = addf2(AZW, h2f2((vx).y)); }

__global__ void gather2_kernel(const __half* __restrict__ hd16,
                               const __half* __restrict__ hc16,
                               float* __restrict__ acc,
                               const int* __restrict__ off_d, const int* __restrict__ csr_d,
                               const int* __restrict__ off_c, const int* __restrict__ csr_c)
{
    const int task = (blockIdx.x * blockDim.x + threadIdx.x) >> 5;
    const int lane = threadIdx.x & 31;
    const int rA = task * 2, rB = rA + 1;

    const uint2 *sA, *sB; const int *oA, *oB, *cAp, *cBp; int ra, rb;
    if (rA < NUM_DRUG) { sA = (const uint2*)hc16; oA = off_d; cAp = csr_d; ra = rA; }
    else               { sA = (const uint2*)hd16; oA = off_c; cAp = csr_c; ra = rA - NUM_DRUG; }
    if (rB < NUM_DRUG) { sB = (const uint2*)hc16; oB = off_d; cBp = csr_d; rb = rB; }
    else               { sB = (const uint2*)hd16; oB = off_c; cBp = csr_c; rb = rB - NUM_DRUG; }

    int jA = oA[ra], eA = oA[ra + 1];
    int jB = oB[rb], eB = oB[rb + 1];

    unsigned long long Axy0 = 0, Axy1 = 0, Azw0 = 0, Azw1 = 0;
    unsigned long long Bxy0 = 0, Bxy1 = 0, Bzw0 = 0, Bzw1 = 0;

    while (jA + 8 <= eA && jB + 8 <= eB) {
        int a0 = cAp[jA],   a1 = cAp[jA+1], a2 = cAp[jA+2], a3 = cAp[jA+3];
        int a4 = cAp[jA+4], a5 = cAp[jA+5], a6 = cAp[jA+6], a7 = cAp[jA+7];
        int b0 = cBp[jB],   b1 = cBp[jB+1], b2 = cBp[jB+2], b3 = cBp[jB+3];
        int b4 = cBp[jB+4], b5 = cBp[jB+5], b6 = cBp[jB+6], b7 = cBp[jB+7];
        uint2 va0 = sA[a0*32+lane], va1 = sA[a1*32+lane], va2 = sA[a2*32+lane], va3 = sA[a3*32+lane];
        uint2 va4 = sA[a4*32+lane], va5 = sA[a5*32+lane], va6 = sA[a6*32+lane], va7 = sA[a7*32+lane];
        uint2 vb0 = sB[b0*32+lane], vb1 = sB[b1*32+lane], vb2 = sB[b2*32+lane], vb3 = sB[b3*32+lane];
        uint2 vb4 = sB[b4*32+lane], vb5 = sB[b5*32+lane], vb6 = sB[b6*32+lane], vb7 = sB[b7*32+lane];
        GACC4(va0, Axy0, Azw0); GACC4(va1, Axy1, Azw1);
        GACC4(va2, Axy0, Azw0); GACC4(va3, Axy1, Azw1);
        GACC4(va4, Axy0, Azw0); GACC4(va5, Axy1, Azw1);
        GACC4(va6, Axy0, Azw0); GACC4(va7, Axy1, Azw1);
        GACC4(vb0, Bxy0, Bzw0); GACC4(vb1, Bxy1, Bzw1);
        GACC4(vb2, Bxy0, Bzw0); GACC4(vb3, Bxy1, Bzw1);
        GACC4(vb4, Bxy0, Bzw0); GACC4(vb5, Bxy1, Bzw1);
        GACC4(vb6, Bxy0, Bzw0); GACC4(vb7, Bxy1, Bzw1);
        jA += 8; jB += 8;
    }
    while (jA + 4 <= eA) {
        int a0 = cAp[jA], a1 = cAp[jA+1], a2 = cAp[jA+2], a3 = cAp[jA+3];
        uint2 v0 = sA[a0*32+lane], v1 = sA[a1*32+lane], v2 = sA[a2*32+lane], v3 = sA[a3*32+lane];
        GACC4(v0, Axy0, Azw0); GACC4(v1, Axy1, Azw1);
        GACC4(v2, Axy0, Azw0); GACC4(v3, Axy1, Azw1);
        jA += 4;
    }
    for (; jA < eA; jA++) { uint2 v = sA[cAp[jA]*32+lane]; GACC4(v, Axy0, Azw0); }
    while (jB + 4 <= eB) {
        int b0 = cBp[jB], b1 = cBp[jB+1], b2 = cBp[jB+2], b3 = cBp[jB+3];
        uint2 v0 = sB[b0*32+lane], v1 = sB[b1*32+lane], v2 = sB[b2*32+lane], v3 = sB[b3*32+lane];
        GACC4(v0, Bxy0, Bzw0); GACC4(v1, Bxy1, Bzw1);
        GACC4(v2, Bxy0, Bzw0); GACC4(v3, Bxy1, Bzw1);
        jB += 4;
    }
    for (; jB < eB; jB++) { uint2 v = sB[cBp[jB]*32+lane]; GACC4(v, Bxy0, Bzw0); }

    unsigned long long AXY = addf2(Axy0, Axy1), AZW = addf2(Azw0, Azw1);
    unsigned long long BXY = addf2(Bxy0, Bxy1), BZW = addf2(Bzw0, Bzw1);
    int dA = eA - oA[ra];
    int dB = eB - oB[rb];
    float invA = 1.0f / (float)(dA < 1 ? 1 : dA);
    float invB = 1.0f / (float)(dB < 1 ? 1 : dB);
    float4 a, b;
    a.x = lo2(AXY) * invA; a.y = hi2(AXY) * invA;
    a.z = lo2(AZW) * invA; a.w = hi2(AZW) * invA;
    b.x = lo2(BXY) * invB; b.y = hi2(BXY) * invB;
    b.z = lo2(BZW) * invB; b.w = hi2(BZW) * invB;
    reinterpret_cast<float4*>(acc)[rA * 32 + lane] = a;
    reinterpret_cast<float4*>(acc)[rB * 32 + lane] = b;
}

// ---------------- GEMM + residual + LN + ReLU (+ optional fp16 mirror) -----
__global__ void __launch_bounds__(256, 2)
gemm_ln_kernel(const float* __restrict__ acc,           // [70000][128] means
               const float* __restrict__ hd_in, const float* __restrict__ hc_in,
               float* __restrict__ hd_out, float* __restrict__ hc_out,
               __half* __restrict__ hd16_out, __half* __restrict__ hc16_out,
               const float* __restrict__ WT_td, const float* __restrict__ WT_dt,
               const float* __restrict__ gd, const float* __restrict__ bd,
               const float* __restrict__ gc, const float* __restrict__ bc,
               int write16)
{
    const bool isD = blockIdx.x < ND_BLOCKS;
    const float* accp = isD ? acc : acc + (size_t)NUM_DRUG * HDIM;
    const float* hold = isD ? hd_in : hc_in;
    float* outp       = isD ? hd_out : hc_out;
    __half* outp16    = isD ? hd16_out : hc16_out;
    const float* WTg  = isD ? WT_td : WT_dt;
    const float* gam  = isD ? gd : gc;
    const float* bet  = isD ? bd : bc;
    const int ng8     = isD ? G8_DRUG : G8_CELL;
    const int nb      = isD ? ND_BLOCKS : (GEMM_BLOCKS - ND_BLOCKS);
    const int bid     = isD ? blockIdx.x : blockIdx.x - ND_BLOCKS;

    extern __shared__ float sm[];
    float* WT = sm;                                  // [128][128]
    const int t = threadIdx.x, lane = t & 31, w = t >> 5;
    float* XS = sm + HDIM * HDIM + w * (8 * HDIM);   // warp-private [8][128]
    const int c0 = 4 * lane;

    {
        const float4* s4 = reinterpret_cast<const float4*>(WTg);
        float4* d4 = reinterpret_cast<float4*>(WT);
        #pragma unroll
        for (int i = t; i < HDIM * HDIM / 4; i += 256) d4[i] = s4[i];
    }
    const float4 g4 = reinterpret_cast<const float4*>(gam)[lane];
    const float4 b4 = reinterpret_cast<const float4*>(bet)[lane];
    __syncthreads();

    const float4* acc4  = reinterpret_cast<const float4*>(accp);
    const float4* hold4 = reinterpret_cast<const float4*>(hold);
    float4* out4        = reinterpret_cast<float4*>(outp);
    uint2* out16        = reinterpret_cast<uint2*>(outp16);

    for (int wg = bid * WARPS + w; wg < ng8; wg += nb * WARPS) {
        const int row0 = wg * 8;

        #pragma unroll
        for (int i = 0; i < 8; i++)
            *reinterpret_cast<float4*>(&XS[i * HDIM + c0]) = acc4[(row0 + i) * 32 + lane];
        __syncwarp();

        unsigned long long acc2[8][2];
        #pragma unroll
        for (int i = 0; i < 8; i++) { acc2[i][0] = 0ull; acc2[i][1] = 0ull; }

        for (int kt = 0; kt < HDIM; kt += 4) {
            float4 xv[8];
            #pragma unroll
            for (int i = 0; i < 8; i++)
                xv[i] = *reinterpret_cast<const float4*>(&XS[i * HDIM + kt]);
            #pragma unroll
            for (int kk = 0; kk < 4; kk++) {
                ulonglong2 wv = *reinterpret_cast<const ulonglong2*>(
                    &WT[(kt + kk) * HDIM + c0]);
                #pragma unroll
                for (int i = 0; i < 8; i++) {
                    float xs = (kk == 0) ? xv[i].x : (kk == 1) ? xv[i].y
                             : (kk == 2) ? xv[i].z : xv[i].w;
                    unsigned long long s2 = splat2(xs);
                    acc2[i][0] = fma2(s2, wv.x, acc2[i][0]);
                    acc2[i][1] = fma2(s2, wv.y, acc2[i][1]);
                }
            }
        }

        #pragma unroll
        for (int i = 0; i < 8; i++) {
            int grow = row0 + i;
            float4 hv = hold4[grow * 32 + lane];
            float y0 = lo2(acc2[i][0]) + hv.x;
            float y1 = hi2(acc2[i][0]) + hv.y;
            float y2 = lo2(acc2[i][1]) + hv.z;
            float y3 = hi2(acc2[i][1]) + hv.w;

            float s = y0 + y1 + y2 + y3;
            float q = y0*y0 + y1*y1 + y2*y2 + y3*y3;
            #pragma unroll
            for (int o = 16; o; o >>= 1) {
                s += __shfl_xor_sync(0xffffffffu, s, o);
                q += __shfl_xor_sync(0xffffffffu, q, o);
            }
            float mu  = s * (1.0f / HDIM);
            float var = q * (1.0f / HDIM) - mu * mu;
            float rs  = rsqrtf(var + 1e-5f);
            float4 o4;
            o4.x = (y0 - mu) * rs * g4.x + b4.x; o4.x = o4.x > 0.f ? o4.x : 0.f;
            o4.y = (y1 - mu) * rs * g4.y + b4.y; o4.y = o4.y > 0.f ? o4.y : 0.f;
            o4.z = (y2 - mu) * rs * g4.z + b4.z; o4.z = o4.z > 0.f ? o4.z : 0.f;
            o4.w = (y3 - mu) * rs * g4.w + b4.w; o4.w = o4.w > 0.f ? o4.w : 0.f;
            out4[grow * 32 + lane] = o4;
            if (write16) {
                uint2 p;
                *reinterpret_cast<__half2*>(&p.x) = __floats2half2_rn(o4.x, o4.y);
                *reinterpret_cast<__half2*>(&p.y) = __floats2half2_rn(o4.z, o4.w);
                out16[grow * 32 + lane] = p;
            }
        }
        __syncwarp();
    }
}

// ---------------- final head -------------------------------------------------
__global__ void final_kernel(const float* __restrict__ hd,
                             const float* __restrict__ hc,
                             const int* __restrict__ did,
                             const int* __restrict__ cid,
                             const float* __restrict__ wf,
                             const float* __restrict__ bf,
                             float* __restrict__ out, int nb)
{
    int warp = (blockIdx.x * blockDim.x + threadIdx.x) >> 5;
    int lane = threadIdx.x & 31;
    if (warp >= nb) return;
    int d = did[warp], c = cid[warp];
    float4 a  = reinterpret_cast<const float4*>(hd)[d * 32 + lane];
    float4 w1 = reinterpret_cast<const float4*>(wf)[lane];
    float4 b4 = reinterpret_cast<const float4*>(hc)[c * 32 + lane];
    float4 w2 = reinterpret_cast<const float4*>(wf)[32 + lane];
    float s = a.x * w1.x + a.y * w1.y + a.z * w1.z + a.w * w1.w
            + b4.x * w2.x + b4.y * w2.y + b4.z * w2.z + b4.w * w2.w;
    #pragma unroll
    for (int o = 16; o; o >>= 1) s += __shfl_xor_sync(0xffffffffu, s, o);
    if (lane == 0) {
        float x = s + bf[0];
        out[warp] = 1.0f / (1.0f + expf(-x));
    }
}

// ---------------------------------------------------------------------------
extern "C" void kernel_launch(void* const* d_in, const int* in_sizes, int n_in,
                              void* d_out, int out_size)
{
    const float* emb_drug  = (const float*)d_in[0];
    const float* emb_cell  = (const float*)d_in[1];
    const float* W_dt      = (const float*)d_in[2];
    const float* W_td      = (const float*)d_in[3];
    const float* ln_drug_g = (const float*)d_in[4];
    const float* ln_drug_b = (const float*)d_in[5];
    const float* ln_cell_g = (const float*)d_in[6];
    const float* ln_cell_b = (const float*)d_in[7];
    const float* W_final_w = (const float*)d_in[8];
    const float* W_final_b = (const float*)d_in[9];
    const int* edge_dt_src = (const int*)d_in[10];
    const int* edge_dt_dst = (const int*)d_in[11];
    const int* edge_td_src = (const int*)d_in[12];
    const int* edge_td_dst = (const int*)d_in[13];
    const int* drug_ids    = (const int*)d_in[14];
    const int* cell_ids    = (const int*)d_in[15];
    float* out = (float*)d_out;

    float *hA_d, *hA_c, *hB_d, *hB_c, *accb, *WT_td, *WT_dt;
    __half *he_d, *he_c, *h1_d, *h1_c;
    int *off_d, *off_c, *cur_d, *cur_c, *rank_td, *rank_dt, *csr_td, *csr_dt;
    cudaGetSymbolAddress((void**)&hA_d,    g_hA_drug);
    cudaGetSymbolAddress((void**)&hA_c,    g_hA_cell);
    cudaGetSymbolAddress((void**)&hB_d,    g_hB_drug);
    cudaGetSymbolAddress((void**)&hB_c,    g_hB_cell);
    cudaGetSymbolAddress((void**)&accb,    g_acc);
    cudaGetSymbolAddress((void**)&he_d,    g_he_drug);
    cudaGetSymbolAddress((void**)&he_c,    g_he_cell);
    cudaGetSymbolAddress((void**)&h1_d,    g_h1_drug);
    cudaGetSymbolAddress((void**)&h1_c,    g_h1_cell);
    cudaGetSymbolAddress((void**)&WT_td,   g_WT_td);
    cudaGetSymbolAddress((void**)&WT_dt,   g_WT_dt);
    cudaGetSymbolAddress((void**)&off_d,   g_off_drug);
    cudaGetSymbolAddress((void**)&off_c,   g_off_cell);
    cudaGetSymbolAddress((void**)&cur_d,   g_cur_drug);
    cudaGetSymbolAddress((void**)&cur_c,   g_cur_cell);
    cudaGetSymbolAddress((void**)&rank_td, g_rank_td);
    cudaGetSymbolAddress((void**)&rank_dt, g_rank_dt);
    cudaGetSymbolAddress((void**)&csr_td,  g_csr_td);
    cudaGetSymbolAddress((void**)&csr_dt,  g_csr_dt);

    cudaFuncSetAttribute(gemm_ln_kernel,
                         cudaFuncAttributeMaxDynamicSharedMemorySize,
                         (int)GEMM_SMEM);

    // dual-row gather: 35000 warp-tasks, 4 warps (128 thr) per block
    const int gather_blocks = ((NUM_DRUG + NUM_CELL) / 2) / 4;   // 8750

    // ---------------- CSR build (rank-based, atomic-free fill) ----------------
    cudaMemsetAsync(cur_d, 0, NUM_DRUG * sizeof(int));
    cudaMemsetAsync(cur_c, 0, NUM_CELL * sizeof(int));
    hist_conv_kernel<<<EB2 + CONVB, 256>>>(edge_td_dst, cur_d, rank_td,
                                           edge_dt_dst, cur_c, rank_dt,
                                           emb_drug, he_d, emb_cell, he_c);
    scan_transpose_kernel<<<4, 1024>>>(cur_d, off_d, cur_c, off_c,
                                       W_td, WT_td, W_dt, WT_dt);
    fill2_kernel<<<(NEDGE + 255) / 256, 256>>>(
        edge_td_src, edge_td_dst, rank_td, off_d, csr_td,
        edge_dt_src, edge_dt_dst, rank_dt, off_c, csr_dt);

    // ---------------- layer 0 ----------------
    gather2_kernel<<<gather_blocks, 128>>>(he_d, he_c, accb,
                                           off_d, csr_td, off_c, csr_dt);
    gemm_ln_kernel<<<GEMM_BLOCKS, 256, GEMM_SMEM>>>(
        accb, emb_drug, emb_cell, hA_d, hA_c, h1_d, h1_c, WT_td, WT_dt,
        ln_drug_g, ln_drug_b, ln_cell_g, ln_cell_b, 1);

    // ---------------- layer 1 ----------------
    gather2_kernel<<<gather_blocks, 128>>>(h1_d, h1_c, accb,
                                           off_d, csr_td, off_c, csr_dt);
    gemm_ln_kernel<<<GEMM_BLOCKS, 256, GEMM_SMEM>>>(
        accb, hA_d, hA_c, hB_d, hB_c, h1_d, h1_c, WT_td, WT_dt,
        ln_drug_g, ln_drug_b, ln_cell_g, ln_cell_b, 0);   // no fp16 mirror

    // ---------------- final head ----------------
    final_kernel<<<(NBATCH * 32) / 256, 256>>>(hB_d, hB_c, drug_ids, cell_ids,
                                               W_final_w, W_final_b, out, NBATCH);
}

// round 17
// speedup vs baseline: 1.2086x; 1.0163x over previous
#include <cuda_runtime.h>
#include <cuda_fp16.h>

#define NUM_DRUG 50000
#define NUM_CELL 20000
#define HDIM     128
#define NEDGE    600000
#define NBATCH   4096

#define G8_DRUG (NUM_DRUG / 8)   // 6250 warp-tiles
#define G8_CELL (NUM_CELL / 8)   // 2500

#define GEMM_BLOCKS 296
#define ND_BLOCKS   212          // drug share of gemm blocks (50k/70k rows)
#define WARPS       8            // 256 threads / block
#define GEMM_SMEM ((HDIM * HDIM + WARPS * 8 * HDIM) * sizeof(float))  // 96 KB

// ---------------- scratch (device globals; no runtime allocation) ----------
__device__ __align__(16) float g_hA_drug[NUM_DRUG * HDIM];
__device__ __align__(16) float g_hA_cell[NUM_CELL * HDIM];
__device__ __align__(16) float g_hB_drug[NUM_DRUG * HDIM];
__device__ __align__(16) float g_hB_cell[NUM_CELL * HDIM];
__device__ __align__(16) __half g_acc16[(NUM_DRUG + NUM_CELL) * HDIM]; // fp16 means
__device__ __align__(16) __half g_he_drug[NUM_DRUG * HDIM];   // fp16 gather tables
__device__ __align__(16) __half g_he_cell[NUM_CELL * HDIM];
__device__ __align__(16) __half g_h1_drug[NUM_DRUG * HDIM];
__device__ __align__(16) __half g_h1_cell[NUM_CELL * HDIM];
__device__ __align__(16) float g_WT_td[HDIM * HDIM];
__device__ __align__(16) float g_WT_dt[HDIM * HDIM];
__device__ int g_off_drug[NUM_DRUG + 1];
__device__ int g_off_cell[NUM_CELL + 1];
__device__ int g_cur_drug[NUM_DRUG];
__device__ int g_cur_cell[NUM_CELL];
__device__ int g_rank_td[NEDGE];   // per-edge rank within its dst (drug side)
__device__ int g_rank_dt[NEDGE];   // per-edge rank within its dst (cell side)
__device__ int g_csr_td[NEDGE];
__device__ int g_csr_dt[NEDGE];

// ---------------- f32x2 helpers --------------------------------------------
__device__ __forceinline__ unsigned long long splat2(float x) {
    unsigned long long r; unsigned xi = __float_as_uint(x);
    asm("mov.b64 %0, {%1, %1};" : "=l"(r) : "r"(xi));
    return r;
}
__device__ __forceinline__ unsigned long long fma2(unsigned long long a,
                                                   unsigned long long b,
                                                   unsigned long long c) {
    unsigned long long d;
    asm("fma.rn.f32x2 %0, %1, %2, %3;" : "=l"(d) : "l"(a), "l"(b), "l"(c));
    return d;
}
__device__ __forceinline__ unsigned long long addf2(unsigned long long a,
                                                    unsigned long long b) {
    unsigned long long d;
    asm("add.rn.f32x2 %0, %1, %2;" : "=l"(d) : "l"(a), "l"(b));
    return d;
}
__device__ __forceinline__ float lo2(unsigned long long v) {
    return __uint_as_float((unsigned)(v & 0xffffffffull));
}
__device__ __forceinline__ float hi2(unsigned long long v) {
    return __uint_as_float((unsigned)(v >> 32));
}
__device__ __forceinline__ unsigned long long h2f2(unsigned h) {
    float2 f = __half22float2(*reinterpret_cast<const __half2*>(&h));
    unsigned long long r;
    asm("mov.b64 %0, {%1, %2};" : "=l"(r) : "f"(f.x), "f"(f.y));
    return r;
}

// ---------------- CSR hist (stores per-edge rank) + emb->fp16 convert ------
#define EB2   ((2 * NEDGE + 255) / 256)                       // 4688 blocks
#define CONVB (((NUM_DRUG + NUM_CELL) * HDIM / 4) / 256)      // 8750 blocks
__global__ void hist_conv_kernel(const int* __restrict__ dstA, int* __restrict__ cntA,
                                 int* __restrict__ rankA,
                                 const int* __restrict__ dstB, int* __restrict__ cntB,
                                 int* __restrict__ rankB,
                                 const float* __restrict__ ed, __half* __restrict__ hd16,
                                 const float* __restrict__ ec, __half* __restrict__ hc16)
{
    long long i = (long long)blockIdx.x * blockDim.x + threadIdx.x;
    if (i < NEDGE) { rankA[i] = atomicAdd(&cntA[dstA[i]], 1); return; }
    if (i < 2 * NEDGE) {
        long long j = i - NEDGE;
        rankB[j] = atomicAdd(&cntB[dstB[j]], 1);
        return;
    }
    long long j = i - 2 * NEDGE;   // float4 index
    const long long nd4 = (long long)NUM_DRUG * HDIM / 4;
    const long long nc4 = (long long)NUM_CELL * HDIM / 4;
    if (j < nd4) {
        float4 v = reinterpret_cast<const float4*>(ed)[j];
        uint2 o;
        *reinterpret_cast<__half2*>(&o.x) = __floats2half2_rn(v.x, v.y);
        *reinterpret_cast<__half2*>(&o.y) = __floats2half2_rn(v.z, v.w);
        reinterpret_cast<uint2*>(hd16)[j] = o;
    } else if (j < nd4 + nc4) {
        long long k = j - nd4;
        float4 v = reinterpret_cast<const float4*>(ec)[k];
        uint2 o;
        *reinterpret_cast<__half2*>(&o.x) = __floats2half2_rn(v.x, v.y);
        *reinterpret_cast<__half2*>(&o.y) = __floats2half2_rn(v.z, v.w);
        reinterpret_cast<uint2*>(hc16)[k] = o;
    }
}

// blocks 0,1: coarsened scans. blocks 2,3: weight transposes.
__global__ void scan_transpose_kernel(const int* __restrict__ cntA, int* __restrict__ offA,
                                      const int* __restrict__ cntB, int* __restrict__ offB,
                                      const float* __restrict__ Wa, float* __restrict__ WTa,
                                      const float* __restrict__ Wb, float* __restrict__ WTb)
{
    int t = threadIdx.x;
    if (blockIdx.x >= 2) {
        const float* W = blockIdx.x == 2 ? Wa : Wb;
        float* WT      = blockIdx.x == 2 ? WTa : WTb;
        #pragma unroll
        for (int i = t; i < HDIM * HDIM; i += 1024) {
            int k = i & 127, out = i >> 7;
            WT[k * HDIM + out] = W[out * HDIM + k];
        }
        return;
    }
    const int* cnt = blockIdx.x == 0 ? cntA : cntB;
    int* off       = blockIdx.x == 0 ? offA : offB;
    const int n    = blockIdx.x == 0 ? NUM_DRUG : NUM_CELL;

    __shared__ int ws[32];
    __shared__ int s_carry;
    int lane = t & 31, w = t >> 5;
    if (t == 0) s_carry = 0;
    __syncthreads();

    for (int base = 0; base < n; base += 1024 * 8) {
        int idx = base + t * 8;
        int v[8];
        #pragma unroll
        for (int j = 0; j < 8; j++)
            v[j] = (idx + j < n) ? cnt[idx + j] : 0;
        #pragma unroll
        for (int j = 1; j < 8; j++) v[j] += v[j - 1];
        int tot = v[7];
        int x = tot;
        #pragma unroll
        for (int o = 1; o < 32; o <<= 1) {
            int y = __shfl_up_sync(0xffffffffu, x, o);
            if (lane >= o) x += y;
        }
        if (lane == 31) ws[w] = x;
        __syncthreads();
        if (w == 0) {
            int s = ws[lane];
            #pragma unroll
            for (int o = 1; o < 32; o <<= 1) {
                int y = __shfl_up_sync(0xffffffffu, s, o);
                if (lane >= o) s += y;
            }
            ws[lane] = s;
        }
        __syncthreads();
        int prefix = (x - tot) + (w ? ws[w - 1] : 0) + s_carry;
        #pragma unroll
        for (int j = 0; j < 8; j++)
            if (idx + j < n) off[idx + j + 1] = prefix + v[j];
        __syncthreads();
        if (t == 0) s_carry += ws[31];
        __syncthreads();
    }
    if (t == 0) off[0] = 0;
}

// atomic-free fill: position = off[dst] + precomputed rank
__global__ void fill2_kernel(const int* __restrict__ srcA, const int* __restrict__ dstA,
                             const int* __restrict__ rankA,
                             const int* __restrict__ offA, int* __restrict__ csrA,
                             const int* __restrict__ srcB, const int* __restrict__ dstB,
                             const int* __restrict__ rankB,
                             const int* __restrict__ offB, int* __restrict__ csrB)
{
    int tid = blockIdx.x * blockDim.x + threadIdx.x;
    int i0 = tid * 2;
    if (i0 < NEDGE) {
        int i1 = i0 + 1;
        int d0 = dstA[i0];
        int d1 = (i1 < NEDGE) ? dstA[i1] : d0;
        int p0 = offA[d0] + rankA[i0];
        int p1 = (i1 < NEDGE) ? (offA[d1] + rankA[i1]) : -1;
        csrA[p0] = srcA[i0];
        if (p1 >= 0) csrA[p1] = srcA[i1];
    } else if (i0 < 2 * NEDGE) {
        int j0 = i0 - NEDGE, j1 = j0 + 1;
        int d0 = dstB[j0];
        int d1 = (j1 < NEDGE) ? dstB[j1] : d0;
        int p0 = offB[d0] + rankB[j0];
        int p1 = (j1 < NEDGE) ? (offB[d1] + rankB[j1]) : -1;
        csrB[p0] = srcB[j0];
        if (p1 >= 0) csrB[p1] = srcB[j1];
    }
}

// ---------------- dual-row gather-mean (fp16 src, fp32 acc, fp16 out) ------
#define GACC4(vx, AXY, AZW) { AXY = addf2(AXY, h2f2((vx).x)); AZW = addf2(AZW, h2f2((vx).y)); }

__global__ void gather2_kernel(const __half* __restrict__ hd16,
                               const __half* __restrict__ hc16,
                               __half* __restrict__ acc16,
                               const int* __restrict__ off_d, const int* __restrict__ csr_d,
                               const int* __restrict__ off_c, const int* __restrict__ csr_c)
{
    const int task = (blockIdx.x * blockDim.x + threadIdx.x) >> 5;
    const int lane = threadIdx.x & 31;
    const int rA = task * 2, rB = rA + 1;

    const uint2 *sA, *sB; const int *oA, *oB, *cAp, *cBp; int ra, rb;
    if (rA < NUM_DRUG) { sA = (const uint2*)hc16; oA = off_d; cAp = csr_d; ra = rA; }
    else               { sA = (const uint2*)hd16; oA = off_c; cAp = csr_c; ra = rA - NUM_DRUG; }
    if (rB < NUM_DRUG) { sB = (const uint2*)hc16; oB = off_d; cBp = csr_d; rb = rB; }
    else               { sB = (const uint2*)hd16; oB = off_c; cBp = csr_c; rb = rB - NUM_DRUG; }

    int jA = oA[ra], eA = oA[ra + 1];
    int jB = oB[rb], eB = oB[rb + 1];

    unsigned long long Axy0 = 0, Axy1 = 0, Azw0 = 0, Azw1 = 0;
    unsigned long long Bxy0 = 0, Bxy1 = 0, Bzw0 = 0, Bzw1 = 0;

    while (jA + 8 <= eA && jB + 8 <= eB) {
        int a0 = cAp[jA],   a1 = cAp[jA+1], a2 = cAp[jA+2], a3 = cAp[jA+3];
        int a4 = cAp[jA+4], a5 = cAp[jA+5], a6 = cAp[jA+6], a7 = cAp[jA+7];
        int b0 = cBp[jB],   b1 = cBp[jB+1], b2 = cBp[jB+2], b3 = cBp[jB+3];
        int b4 = cBp[jB+4], b5 = cBp[jB+5], b6 = cBp[jB+6], b7 = cBp[jB+7];
        uint2 va0 = sA[a0*32+lane], va1 = sA[a1*32+lane], va2 = sA[a2*32+lane], va3 = sA[a3*32+lane];
        uint2 va4 = sA[a4*32+lane], va5 = sA[a5*32+lane], va6 = sA[a6*32+lane], va7 = sA[a7*32+lane];
        uint2 vb0 = sB[b0*32+lane], vb1 = sB[b1*32+lane], vb2 = sB[b2*32+lane], vb3 = sB[b3*32+lane];
        uint2 vb4 = sB[b4*32+lane], vb5 = sB[b5*32+lane], vb6 = sB[b6*32+lane], vb7 = sB[b7*32+lane];
        GACC4(va0, Axy0, Azw0); GACC4(va1, Axy1, Azw1);
        GACC4(va2, Axy0, Azw0); GACC4(va3, Axy1, Azw1);
        GACC4(va4, Axy0, Azw0); GACC4(va5, Axy1, Azw1);
        GACC4(va6, Axy0, Azw0); GACC4(va7, Axy1, Azw1);
        GACC4(vb0, Bxy0, Bzw0); GACC4(vb1, Bxy1, Bzw1);
        GACC4(vb2, Bxy0, Bzw0); GACC4(vb3, Bxy1, Bzw1);
        GACC4(vb4, Bxy0, Bzw0); GACC4(vb5, Bxy1, Bzw1);
        GACC4(vb6, Bxy0, Bzw0); GACC4(vb7, Bxy1, Bzw1);
        jA += 8; jB += 8;
    }
    while (jA + 4 <= eA) {
        int a0 = cAp[jA], a1 = cAp[jA+1], a2 = cAp[jA+2], a3 = cAp[jA+3];
        uint2 v0 = sA[a0*32+lane], v1 = sA[a1*32+lane], v2 = sA[a2*32+lane], v3 = sA[a3*32+lane];
        GACC4(v0, Axy0, Azw0); GACC4(v1, Axy1, Azw1);
        GACC4(v2, Axy0, Azw0); GACC4(v3, Axy1, Azw1);
        jA += 4;
    }
    for (; jA < eA; jA++) { uint2 v = sA[cAp[jA]*32+lane]; GACC4(v, Axy0, Azw0); }
    while (jB + 4 <= eB) {
        int b0 = cBp[jB], b1 = cBp[jB+1], b2 = cBp[jB+2], b3 = cBp[jB+3];
        uint2 v0 = sB[b0*32+lane], v1 = sB[b1*32+lane], v2 = sB[b2*32+lane], v3 = sB[b3*32+lane];
        GACC4(v0, Bxy0, Bzw0); GACC4(v1, Bxy1, Bzw1);
        GACC4(v2, Bxy0, Bzw0); GACC4(v3, Bxy1, Bzw1);
        jB += 4;
    }
    for (; jB < eB; jB++) { uint2 v = sB[cBp[jB]*32+lane]; GACC4(v, Bxy0, Bzw0); }

    unsigned long long AXY = addf2(Axy0, Axy1), AZW = addf2(Azw0, Azw1);
    unsigned long long BXY = addf2(Bxy0, Bxy1), BZW = addf2(Bzw0, Bzw1);
    int dA = eA - oA[ra];
    int dB = eB - oB[rb];
    float invA = 1.0f / (float)(dA < 1 ? 1 : dA);
    float invB = 1.0f / (float)(dB < 1 ? 1 : dB);
    uint2 pa, pb;
    *reinterpret_cast<__half2*>(&pa.x) = __floats2half2_rn(lo2(AXY) * invA, hi2(AXY) * invA);
    *reinterpret_cast<__half2*>(&pa.y) = __floats2half2_rn(lo2(AZW) * invA, hi2(AZW) * invA);
    *reinterpret_cast<__half2*>(&pb.x) = __floats2half2_rn(lo2(BXY) * invB, hi2(BXY) * invB);
    *reinterpret_cast<__half2*>(&pb.y) = __floats2half2_rn(lo2(BZW) * invB, hi2(BZW) * invB);
    reinterpret_cast<uint2*>(acc16)[rA * 32 + lane] = pa;
    reinterpret_cast<uint2*>(acc16)[rB * 32 + lane] = pb;
}

// ---------------- GEMM + residual + LN + ReLU (+ optional fp16 mirror) -----
__global__ void __launch_bounds__(256, 2)
gemm_ln_kernel(const __half* __restrict__ acc16,        // [70000][128] fp16 means
               const float* __restrict__ hd_in, const float* __restrict__ hc_in,
               float* __restrict__ hd_out, float* __restrict__ hc_out,
               __half* __restrict__ hd16_out, __half* __restrict__ hc16_out,
               const float* __restrict__ WT_td, const float* __restrict__ WT_dt,
               const float* __restrict__ gd, const float* __restrict__ bd,
               const float* __restrict__ gc, const float* __restrict__ bc,
               int write16)
{
    const bool isD = blockIdx.x < ND_BLOCKS;
    const __half* accp = acc16 + (isD ? 0 : (size_t)NUM_DRUG * HDIM);
    const float* hold = isD ? hd_in : hc_in;
    float* outp       = isD ? hd_out : hc_out;
    __half* outp16    = isD ? hd16_out : hc16_out;
    const float* WTg  = isD ? WT_td : WT_dt;
    const float* gam  = isD ? gd : gc;
    const float* bet  = isD ? bd : bc;
    const int ng8     = isD ? G8_DRUG : G8_CELL;
    const int nb      = isD ? ND_BLOCKS : (GEMM_BLOCKS - ND_BLOCKS);
    const int bid     = isD ? blockIdx.x : blockIdx.x - ND_BLOCKS;

    extern __shared__ float sm[];
    float* WT = sm;                                  // [128][128]
    const int t = threadIdx.x, lane = t & 31, w = t >> 5;
    float* XS = sm + HDIM * HDIM + w * (8 * HDIM);   // warp-private [8][128]
    const int c0 = 4 * lane;

    {
        const float4* s4 = reinterpret_cast<const float4*>(WTg);
        float4* d4 = reinterpret_cast<float4*>(WT);
        #pragma unroll
        for (int i = t; i < HDIM * HDIM / 4; i += 256) d4[i] = s4[i];
    }
    const float4 g4 = reinterpret_cast<const float4*>(gam)[lane];
    const float4 b4 = reinterpret_cast<const float4*>(bet)[lane];
    __syncthreads();

    const uint2* acc2h  = reinterpret_cast<const uint2*>(accp);   // 4 halves/lane
    const float4* hold4 = reinterpret_cast<const float4*>(hold);
    float4* out4        = reinterpret_cast<float4*>(outp);
    uint2* out16        = reinterpret_cast<uint2*>(outp16);

    for (int wg = bid * WARPS + w; wg < ng8; wg += nb * WARPS) {
        const int row0 = wg * 8;

        // stage 8 fp16 mean rows into XS as fp32 (cvt outside inner loop)
        #pragma unroll
        for (int i = 0; i < 8; i++) {
            uint2 v = acc2h[(row0 + i) * 32 + lane];
            unsigned long long f01 = h2f2(v.x);
            unsigned long long f23 = h2f2(v.y);
            float4 x4;
            x4.x = lo2(f01); x4.y = hi2(f01);
            x4.z = lo2(f23); x4.w = hi2(f23);
            *reinterpret_cast<float4*>(&XS[i * HDIM + c0]) = x4;
        }
        __syncwarp();

        unsigned long long acc2[8][2];
        #pragma unroll
        for (int i = 0; i < 8; i++) { acc2[i][0] = 0ull; acc2[i][1] = 0ull; }

        for (int kt = 0; kt < HDIM; kt += 4) {
            float4 xv[8];
            #pragma unroll
            for (int i = 0; i < 8; i++)
                xv[i] = *reinterpret_cast<const float4*>(&XS[i * HDIM + kt]);
            #pragma unroll
            for (int kk = 0; kk < 4; kk++) {
                ulonglong2 wv = *reinterpret_cast<const ulonglong2*>(
                    &WT[(kt + kk) * HDIM + c0]);
                #pragma unroll
                for (int i = 0; i < 8; i++) {
                    float xs = (kk == 0) ? xv[i].x : (kk == 1) ? xv[i].y
                             : (kk == 2) ? xv[i].z : xv[i].w;
                    unsigned long long s2 = splat2(xs);
                    acc2[i][0] = fma2(s2, wv.x, acc2[i][0]);
                    acc2[i][1] = fma2(s2, wv.y, acc2[i][1]);
                }
            }
        }

        #pragma unroll
        for (int i = 0; i < 8; i++) {
            int grow = row0 + i;
            float4 hv = hold4[grow * 32 + lane];
            float y0 = lo2(acc2[i][0]) + hv.x;
            float y1 = hi2(acc2[i][0]) + hv.y;
            float y2 = lo2(acc2[i][1]) + hv.z;
            float y3 = hi2(acc2[i][1]) + hv.w;

            float s = y0 + y1 + y2 + y3;
            float q = y0*y0 + y1*y1 + y2*y2 + y3*y3;
            #pragma unroll
            for (int o = 16; o; o >>= 1) {
                s += __shfl_xor_sync(0xffffffffu, s, o);
                q += __shfl_xor_sync(0xffffffffu, q, o);
            }
            float mu  = s * (1.0f / HDIM);
            float var = q * (1.0f / HDIM) - mu * mu;
            float rs  = rsqrtf(var + 1e-5f);
            float4 o4;
            o4.x = (y0 - mu) * rs * g4.x + b4.x; o4.x = o4.x > 0.f ? o4.x : 0.f;
            o4.y = (y1 - mu) * rs * g4.y + b4.y; o4.y = o4.y > 0.f ? o4.y : 0.f;
            o4.z = (y2 - mu) * rs * g4.z + b4.z; o4.z = o4.z > 0.f ? o4.z : 0.f;
            o4.w = (y3 - mu) * rs * g4.w + b4.w; o4.w = o4.w > 0.f ? o4.w : 0.f;
            out4[grow * 32 + lane] = o4;
            if (write16) {
                uint2 p;
                *reinterpret_cast<__half2*>(&p.x) = __floats2half2_rn(o4.x, o4.y);
                *reinterpret_cast<__half2*>(&p.y) = __floats2half2_rn(o4.z, o4.w);
                out16[grow * 32 + lane] = p;
            }
        }
        __syncwarp();
    }
}

// ---------------- final head -------------------------------------------------
__global__ void final_kernel(const float* __restrict__ hd,
                             const float* __restrict__ hc,
                             const int* __restrict__ did,
                             const int* __restrict__ cid,
                             const float* __restrict__ wf,
                             const float* __restrict__ bf,
                             float* __restrict__ out, int nb)
{
    int warp = (blockIdx.x * blockDim.x + threadIdx.x) >> 5;
    int lane = threadIdx.x & 31;
    if (warp >= nb) return;
    int d = did[warp], c = cid[warp];
    float4 a  = reinterpret_cast<const float4*>(hd)[d * 32 + lane];
    float4 w1 = reinterpret_cast<const float4*>(wf)[lane];
    float4 b4 = reinterpret_cast<const float4*>(hc)[c * 32 + lane];
    float4 w2 = reinterpret_cast<const float4*>(wf)[32 + lane];
    float s = a.x * w1.x + a.y * w1.y + a.z * w1.z + a.w * w1.w
            + b4.x * w2.x + b4.y * w2.y + b4.z * w2.z + b4.w * w2.w;
    #pragma unroll
    for (int o = 16; o; o >>= 1) s += __shfl_xor_sync(0xffffffffu, s, o);
    if (lane == 0) {
        float x = s + bf[0];
        out[warp] = 1.0f / (1.0f + expf(-x));
    }
}

// ---------------------------------------------------------------------------
extern "C" void kernel_launch(void* const* d_in, const int* in_sizes, int n_in,
                              void* d_out, int out_size)
{
    const float* emb_drug  = (const float*)d_in[0];
    const float* emb_cell  = (const float*)d_in[1];
    const float* W_dt      = (const float*)d_in[2];
    const float* W_td      = (const float*)d_in[3];
    const float* ln_drug_g = (const float*)d_in[4];
    const float* ln_drug_b = (const float*)d_in[5];
    const float* ln_cell_g = (const float*)d_in[6];
    const float* ln_cell_b = (const float*)d_in[7];
    const float* W_final_w = (const float*)d_in[8];
    const float* W_final_b = (const float*)d_in[9];
    const int* edge_dt_src = (const int*)d_in[10];
    const int* edge_dt_dst = (const int*)d_in[11];
    const int* edge_td_src = (const int*)d_in[12];
    const int* edge_td_dst = (const int*)d_in[13];
    const int* drug_ids    = (const int*)d_in[14];
    const int* cell_ids    = (const int*)d_in[15];
    float* out = (float*)d_out;

    float *hA_d, *hA_c, *hB_d, *hB_c, *WT_td, *WT_dt;
    __half *acc16, *he_d, *he_c, *h1_d, *h1_c;
    int *off_d, *off_c, *cur_d, *cur_c, *rank_td, *rank_dt, *csr_td, *csr_dt;
    cudaGetSymbolAddress((void**)&hA_d,    g_hA_drug);
    cudaGetSymbolAddress((void**)&hA_c,    g_hA_cell);
    cudaGetSymbolAddress((void**)&hB_d,    g_hB_drug);
    cudaGetSymbolAddress((void**)&hB_c,    g_hB_cell);
    cudaGetSymbolAddress((void**)&acc16,   g_acc16);
    cudaGetSymbolAddress((void**)&he_d,    g_he_drug);
    cudaGetSymbolAddress((void**)&he_c,    g_he_cell);
    cudaGetSymbolAddress((void**)&h1_d,    g_h1_drug);
    cudaGetSymbolAddress((void**)&h1_c,    g_h1_cell);
    cudaGetSymbolAddress((void**)&WT_td,   g_WT_td);
    cudaGetSymbolAddress((void**)&WT_dt,   g_WT_dt);
    cudaGetSymbolAddress((void**)&off_d,   g_off_drug);
    cudaGetSymbolAddress((void**)&off_c,   g_off_cell);
    cudaGetSymbolAddress((void**)&cur_d,   g_cur_drug);
    cudaGetSymbolAddress((void**)&cur_c,   g_cur_cell);
    cudaGetSymbolAddress((void**)&rank_td, g_rank_td);
    cudaGetSymbolAddress((void**)&rank_dt, g_rank_dt);
    cudaGetSymbolAddress((void**)&csr_td,  g_csr_td);
    cudaGetSymbolAddress((void**)&csr_dt,  g_csr_dt);

    cudaFuncSetAttribute(gemm_ln_kernel,
                         cudaFuncAttributeMaxDynamicSharedMemorySize,
                         (int)GEMM_SMEM);

    // dual-row gather: 35000 warp-tasks, 4 warps (128 thr) per block
    const int gather_blocks = ((NUM_DRUG + NUM_CELL) / 2) / 4;   // 8750

    // ---------------- CSR build (rank-based, atomic-free fill) ----------------
    cudaMemsetAsync(cur_d, 0, NUM_DRUG * sizeof(int));
    cudaMemsetAsync(cur_c, 0, NUM_CELL * sizeof(int));
    hist_conv_kernel<<<EB2 + CONVB, 256>>>(edge_td_dst, cur_d, rank_td,
                                           edge_dt_dst, cur_c, rank_dt,
                                           emb_drug, he_d, emb_cell, he_c);
    scan_transpose_kernel<<<4, 1024>>>(cur_d, off_d, cur_c, off_c,
                                       W_td, WT_td, W_dt, WT_dt);
    fill2_kernel<<<(NEDGE + 255) / 256, 256>>>(
        edge_td_src, edge_td_dst, rank_td, off_d, csr_td,
        edge_dt_src, edge_dt_dst, rank_dt, off_c, csr_dt);

    // ---------------- layer 0 ----------------
    gather2_kernel<<<gather_blocks, 128>>>(he_d, he_c, acc16,
                                           off_d, csr_td, off_c, csr_dt);
    gemm_ln_kernel<<<GEMM_BLOCKS, 256, GEMM_SMEM>>>(
        acc16, emb_drug, emb_cell, hA_d, hA_c, h1_d, h1_c, WT_td, WT_dt,
        ln_drug_g, ln_drug_b, ln_cell_g, ln_cell_b, 1);

    // ---------------- layer 1 ----------------
    gather2_kernel<<<gather_blocks, 128>>>(h1_d, h1_c, acc16,
                                           off_d, csr_td, off_c, csr_dt);
    gemm_ln_kernel<<<GEMM_BLOCKS, 256, GEMM_SMEM>>>(
        acc16, hA_d, hA_c, hB_d, hB_c, h1_d, h1_c, WT_td, WT_dt,
        ln_drug_g, ln_drug_b, ln_cell_g, ln_cell_b, 0);   // no fp16 mirror

    // ---------------- final head ----------------
    final_kernel<<<(NBATCH * 32) / 256, 256>>>(hB_d, hB_c, drug_ids, cell_ids,
                                               W_final_w, W_final_b, out, NBATCH);
}